// round 15
// baseline (speedup 1.0000x reference)
#include <cuda_runtime.h>
#include <cuda_bf16.h>
#include <cstdint>
#include <cstddef>

// ---------------------------------------------------------------------------
#define NB    32
#define NPIX  4096
#define NTOK  (NB*NPIX)   // 131072
#define CIN   960
#define C3    96
#define NG    12
#define HW    64

typedef __nv_bfloat16 bf16;

// ---------------------------------------------------------------------------
// Scratch (device globals)
// ---------------------------------------------------------------------------
__device__ bf16  g_xn   [(size_t)NTOK * CIN];          // LN'd x, [token][960] bf16 (251 MB)
__device__ bf16  g_multi[(size_t)NB * 288 * NPIX];     // [b][ch][n] bf16 (75 MB)
__device__ bf16  g_att  [(size_t)NB * NPIX * C3];      // [b][n][ch] bf16 (25 MB) token-major
__device__ bf16  g_wqkv [C3 * CIN];
__device__ bf16  g_wproj[CIN * C3];
__device__ float g_vkp  [NB * NG * 4 * 72];            // vk partials (4 pixel chunks)

// ---------------------------------------------------------------------------
// K1: LayerNorm, warp-per-token, register-resident, streaming cache hints.
// Also performs weight fp32->bf16 conversion (merged prep_weights).
// ---------------------------------------------------------------------------
template<int CSZ>
__device__ __forceinline__ void norm_seg(const float* __restrict__ p,
                                         const float* __restrict__ gw,
                                         const float* __restrict__ bw,
                                         bf16* __restrict__ dst, int lane) {
    constexpr int NQ = CSZ / 4;
    constexpr int NI = (NQ + 31) / 32;
    float4 v[NI];
    float sum = 0.f, sq = 0.f;
    #pragma unroll
    for (int i = 0; i < NI; i++) {
        int q = lane + i * 32;
        if ((NQ % 32 == 0) || q < NQ) {
            v[i] = __ldcs(reinterpret_cast<const float4*>(p + q * 4));
            sum += v[i].x + v[i].y + v[i].z + v[i].w;
            sq  += v[i].x * v[i].x + v[i].y * v[i].y + v[i].z * v[i].z + v[i].w * v[i].w;
        }
    }
    #pragma unroll
    for (int off = 16; off > 0; off >>= 1) {
        sum += __shfl_xor_sync(0xffffffffu, sum, off);
        sq  += __shfl_xor_sync(0xffffffffu, sq,  off);
    }
    float m = sum / (float)CSZ;
    float r = rsqrtf(sq / (float)CSZ - m * m + 1e-6f);
    #pragma unroll
    for (int i = 0; i < NI; i++) {
        int q = lane + i * 32;
        if ((NQ % 32 == 0) || q < NQ) {
            float4 gv = *reinterpret_cast<const float4*>(gw + q * 4);
            float4 bv = *reinterpret_cast<const float4*>(bw + q * 4);
            float f0 = (v[i].x - m) * (r * gv.x) + bv.x;
            float f1 = (v[i].y - m) * (r * gv.y) + bv.y;
            float f2 = (v[i].z - m) * (r * gv.z) + bv.z;
            float f3 = (v[i].w - m) * (r * gv.w) + bv.w;
            __nv_bfloat162 p0 = __floats2bfloat162_rn(f0, f1);
            __nv_bfloat162 p1 = __floats2bfloat162_rn(f2, f3);
            uint2 u = make_uint2(*reinterpret_cast<uint32_t*>(&p0),
                                 *reinterpret_cast<uint32_t*>(&p1));
            __stcs(reinterpret_cast<uint2*>(dst + q * 4), u);
        }
    }
}

__global__ void __launch_bounds__(256) norm_kernel(
    const float* __restrict__ x1, const float* __restrict__ x2, const float* __restrict__ x3,
    const float* __restrict__ g1, const float* __restrict__ b1,
    const float* __restrict__ g2, const float* __restrict__ b2,
    const float* __restrict__ g3, const float* __restrict__ b3,
    const float* __restrict__ qkv_w, const float* __restrict__ proj_w) {
    int gtid = blockIdx.x * 256 + threadIdx.x;
    if (gtid < C3 * CIN) {
        g_wqkv[gtid]  = __float2bfloat16(qkv_w[gtid]);
        g_wproj[gtid] = __float2bfloat16(proj_w[gtid]);
    }
    int t = gtid >> 5;
    int lane = threadIdx.x & 31;
    bf16* dst = g_xn + (size_t)t * CIN;
    norm_seg<192>(x1 + (size_t)t * 192, g1, b1, dst,       lane);
    norm_seg<256>(x2 + (size_t)t * 256, g2, b2, dst + 192, lane);
    norm_seg<512>(x3 + (size_t)t * 512, g3, b3, dst + 448, lane);
}

// ---------------------------------------------------------------------------
// mma.sync m16n8k16 bf16 helper
// ---------------------------------------------------------------------------
__device__ __forceinline__ void mma_bf16(float* c, const uint32_t* a, const uint32_t* b) {
    asm volatile(
        "mma.sync.aligned.m16n8k16.row.col.f32.bf16.bf16.f32 "
        "{%0,%1,%2,%3}, {%4,%5,%6,%7}, {%8,%9}, {%0,%1,%2,%3};\n"
        : "+f"(c[0]), "+f"(c[1]), "+f"(c[2]), "+f"(c[3])
        : "r"(a[0]), "r"(a[1]), "r"(a[2]), "r"(a[3]), "r"(b[0]), "r"(b[1]));
}

__device__ __forceinline__ void cp16(uint32_t smem_addr, const void* gptr) {
    asm volatile("cp.async.cg.shared.global [%0], [%1], 16;\n"
                 :: "r"(smem_addr), "l"(gptr));
}

// ---------------------------------------------------------------------------
// K2: qkv GEMM (M=131072, N=96, K=960), bf16 A from g_xn, ldmatrix fragments,
// 2-stage cp.async double-buffered K-loop.
// ---------------------------------------------------------------------------
__global__ void __launch_bounds__(256) qkv_gemm_kernel() {
    __shared__ union {
        struct { bf16 A[2][128][40]; bf16 W[2][96][40]; } s;  // 35840 B
        bf16 C[96][136];                                       // 26112 B
    } sm;
    const int tid  = threadIdx.x;
    const int warp = tid >> 5, lane = tid & 31;
    const int warpM = warp & 3, warpN = warp >> 2;
    const int g = lane >> 2, tg = lane & 3;
    const int token0 = blockIdx.x * 128;
    const bf16* An = g_xn + (size_t)token0 * CIN;

    const int lr = lane & 7;
    const int lg = lane >> 3;
    const int a_row = warpM * 32 + lr + ((lane >> 3) & 1) * 8;
    const int a_col = (lane >> 4) * 8;
    const int b_blk = (lg >> 1);
    const int b_col = (lg & 1) * 8;

    uint32_t Abase, Wbase;
    {
        uint64_t a64 = __cvta_generic_to_shared(&sm.s.A[0][0][0]);
        uint64_t w64 = __cvta_generic_to_shared(&sm.s.W[0][0][0]);
        Abase = (uint32_t)a64;
        Wbase = (uint32_t)w64;
    }
    const int la_row = tid >> 2, la_q = tid & 3;

    float acc[2][6][4];
    #pragma unroll
    for (int mr = 0; mr < 2; mr++)
        #pragma unroll
        for (int nb = 0; nb < 6; nb++)
            #pragma unroll
            for (int q = 0; q < 4; q++) acc[mr][nb][q] = 0.f;

    auto load_tile = [&](int kt, int sb) {
        const int k0 = kt * 32;
        const uint32_t Aoff = Abase + (uint32_t)(sb * 128 * 40 * 2);
        const uint32_t Woff = Wbase + (uint32_t)(sb * 96 * 40 * 2);
        cp16(Aoff + (uint32_t)((la_row * 40 + la_q * 8) * 2),
             An + (size_t)la_row * CIN + k0 + la_q * 8);
        cp16(Aoff + (uint32_t)(((la_row + 64) * 40 + la_q * 8) * 2),
             An + (size_t)(la_row + 64) * CIN + k0 + la_q * 8);
        cp16(Woff + (uint32_t)((la_row * 40 + la_q * 8) * 2),
             g_wqkv + (size_t)la_row * CIN + k0 + la_q * 8);
        if (tid < 128) {
            int o = 64 + (tid >> 2), q = tid & 3;
            cp16(Woff + (uint32_t)((o * 40 + q * 8) * 2),
                 g_wqkv + (size_t)o * CIN + k0 + q * 8);
        }
    };

    load_tile(0, 0);
    asm volatile("cp.async.commit_group;\n" ::: "memory");

    for (int kt = 0; kt < 30; kt++) {
        const int sb = kt & 1;
        if (kt < 29) {
            load_tile(kt + 1, sb ^ 1);
            asm volatile("cp.async.commit_group;\n" ::: "memory");
            asm volatile("cp.async.wait_group 1;\n" ::: "memory");
        } else {
            asm volatile("cp.async.wait_group 0;\n" ::: "memory");
        }
        __syncthreads();
        const uint32_t Aoff = Abase + (uint32_t)(sb * 128 * 40 * 2);
        const uint32_t Woff = Wbase + (uint32_t)(sb * 96 * 40 * 2);
        #pragma unroll
        for (int ks = 0; ks < 32; ks += 16) {
            uint32_t afr[2][4], bfr[6][2];
            #pragma unroll
            for (int mr = 0; mr < 2; mr++) {
                uint32_t addr = Aoff + (uint32_t)(((a_row + mr * 16) * 40 + ks + a_col) * 2);
                asm volatile(
                    "ldmatrix.sync.aligned.m8n8.x4.shared.b16 {%0,%1,%2,%3}, [%4];"
                    : "=r"(afr[mr][0]), "=r"(afr[mr][1]), "=r"(afr[mr][2]), "=r"(afr[mr][3])
                    : "r"(addr));
            }
            #pragma unroll
            for (int nb2 = 0; nb2 < 3; nb2++) {
                uint32_t addr = Woff + (uint32_t)((((warpN * 48 + (nb2 * 2 + b_blk) * 8 + lr) * 40)
                                                    + ks + b_col) * 2);
                asm volatile(
                    "ldmatrix.sync.aligned.m8n8.x4.shared.b16 {%0,%1,%2,%3}, [%4];"
                    : "=r"(bfr[nb2 * 2][0]), "=r"(bfr[nb2 * 2][1]),
                      "=r"(bfr[nb2 * 2 + 1][0]), "=r"(bfr[nb2 * 2 + 1][1])
                    : "r"(addr));
            }
            #pragma unroll
            for (int mr = 0; mr < 2; mr++)
                #pragma unroll
                for (int nb = 0; nb < 6; nb++)
                    mma_bf16(acc[mr][nb], afr[mr], bfr[nb]);
        }
        __syncthreads();
    }
    #pragma unroll
    for (int mr = 0; mr < 2; mr++)
        #pragma unroll
        for (int nb = 0; nb < 6; nb++) {
            int oo = warpN * 48 + nb * 8 + tg * 2;
            int t0 = warpM * 32 + mr * 16 + g;
            sm.C[oo    ][t0    ] = __float2bfloat16(acc[mr][nb][0]);
            sm.C[oo + 1][t0    ] = __float2bfloat16(acc[mr][nb][1]);
            sm.C[oo    ][t0 + 8] = __float2bfloat16(acc[mr][nb][2]);
            sm.C[oo + 1][t0 + 8] = __float2bfloat16(acc[mr][nb][3]);
        }
    __syncthreads();
    const int bb = token0 >> 12;
    const int n0 = token0 & (NPIX - 1);
    #pragma unroll
    for (int i = 0; i < 6; i++) {
        int idx = tid + i * 256;
        int o = idx >> 4, q = idx & 15;
        uint4 v = *reinterpret_cast<const uint4*>(&sm.C[o][q * 8]);
        *reinterpret_cast<uint4*>(g_multi + ((size_t)bb * 288 + o) * NPIX + n0 + q * 8) = v;
    }
}

// ---------------------------------------------------------------------------
// K3: MERGED dw3+pw3 and dw5+pw5 (measured 55us; unchanged).
// ---------------------------------------------------------------------------
__global__ void __launch_bounds__(256, 4) dwpw_merged_kernel(
        const float* __restrict__ dw3_w, const float* __restrict__ pw3_w,
        const float* __restrict__ dw5_w, const float* __restrict__ pw5_w) {
    constexpr int T = 36;
    __shared__ float sin_[8][T][T];
    __shared__ float wd3[8][9], wd5[8][25];
    __shared__ __nv_bfloat162 wp3p[8][8], wp5p[8][8];
    const int b = blockIdx.z, g = blockIdx.y, tile = blockIdx.x;
    const int ty0 = (tile >> 1) * 32, tx0 = (tile & 1) * 32;
    const int tid = threadIdx.x;
    const bf16* src = g_multi + ((size_t)b * 288 + g * 8) * NPIX;

    for (int idx = tid; idx < 8 * T * T; idx += 256) {
        int ch = idx / (T * T); int rem = idx - ch * T * T;
        int yy = rem / T, xx = rem - yy * T;
        int gy = ty0 + yy - 2, gx = tx0 + xx - 2;
        float v = 0.f;
        if (gy >= 0 && gy < HW && gx >= 0 && gx < HW)
            v = __bfloat162float(src[ch * NPIX + gy * HW + gx]);
        sin_[ch][yy][xx] = v;
    }
    if (tid < 72) { int ch = tid / 9, kk = tid % 9; wd3[ch][kk] = dw3_w[(g * 8 + ch) * 9 + kk]; }
    else if (tid < 136) {
        int t = tid - 72;
        wp3p[t & 7][t >> 3] = __float2bfloat162_rn(pw3_w[(g * 8 + (t >> 3)) * 8 + (t & 7)]);
    } else if (tid < 200) {
        int t = tid - 136;
        wp5p[t & 7][t >> 3] = __float2bfloat162_rn(pw5_w[(g * 8 + (t >> 3)) * 8 + (t & 7)]);
    }
    for (int t = tid; t < 200; t += 256) {
        int ch = t / 25, kk = t % 25;
        wd5[ch][kk] = dw5_w[(g * 8 + ch) * 25 + kk];
    }
    __syncthreads();

    const int py  = tid >> 3;
    const int px0 = (tid & 7) * 4;
    __nv_bfloat162 o3p[2][8], o5p[2][8];
    const __nv_bfloat162 z2 = __float2bfloat162_rn(0.f);
    #pragma unroll
    for (int j = 0; j < 2; j++)
        #pragma unroll
        for (int o = 0; o < 8; o++) { o3p[j][o] = z2; o5p[j][o] = z2; }

    #pragma unroll 1
    for (int ch = 0; ch < 8; ch++) {
        float s5[4] = {0.f, 0.f, 0.f, 0.f};
        float s3[4] = {0.f, 0.f, 0.f, 0.f};
        #pragma unroll
        for (int r = 0; r < 5; r++) {
            float4 a = *reinterpret_cast<const float4*>(&sin_[ch][py + r][px0]);
            float4 c4 = *reinterpret_cast<const float4*>(&sin_[ch][py + r][px0 + 4]);
            float w[8] = {a.x, a.y, a.z, a.w, c4.x, c4.y, c4.z, c4.w};
            #pragma unroll
            for (int j = 0; j < 4; j++) {
                float t = 0.f;
                #pragma unroll
                for (int c = 0; c < 5; c++) t = fmaf(w[c + j], wd5[ch][r * 5 + c], t);
                s5[j] += t;
            }
            if (r >= 1 && r <= 3) {
                #pragma unroll
                for (int j = 0; j < 4; j++) {
                    float t = 0.f;
                    #pragma unroll
                    for (int c = 0; c < 3; c++) t = fmaf(w[c + j + 1], wd3[ch][(r - 1) * 3 + c], t);
                    s3[j] += t;
                }
            }
        }
        __nv_bfloat162 s3a = __floats2bfloat162_rn(s3[0], s3[1]);
        __nv_bfloat162 s3b = __floats2bfloat162_rn(s3[2], s3[3]);
        __nv_bfloat162 s5a = __floats2bfloat162_rn(s5[0], s5[1]);
        __nv_bfloat162 s5b = __floats2bfloat162_rn(s5[2], s5[3]);
        #pragma unroll
        for (int o = 0; o < 8; o++) {
            o3p[0][o] = __hfma2(wp3p[ch][o], s3a, o3p[0][o]);
            o3p[1][o] = __hfma2(wp3p[ch][o], s3b, o3p[1][o]);
            o5p[0][o] = __hfma2(wp5p[ch][o], s5a, o5p[0][o]);
            o5p[1][o] = __hfma2(wp5p[ch][o], s5b, o5p[1][o]);
        }
    }
    bf16* dst3 = g_multi + ((size_t)b * 288 +  96 + g * 8) * NPIX;
    bf16* dst5 = g_multi + ((size_t)b * 288 + 192 + g * 8) * NPIX;
    int n = (ty0 + py) * HW + (tx0 + px0);
    #pragma unroll
    for (int o = 0; o < 8; o++) {
        uint2 u3 = make_uint2(*reinterpret_cast<uint32_t*>(&o3p[0][o]),
                              *reinterpret_cast<uint32_t*>(&o3p[1][o]));
        *reinterpret_cast<uint2*>(dst3 + o * NPIX + n) = u3;
        uint2 u5 = make_uint2(*reinterpret_cast<uint32_t*>(&o5p[0][o]),
                              *reinterpret_cast<uint32_t*>(&o5p[1][o]));
        *reinterpret_cast<uint2*>(dst5 + o * NPIX + n) = u5;
    }
}

// ---------------------------------------------------------------------------
// K4a: vk partials per (b, g, z of 4). uint2 loads, 4 px/thread, single pass.
// ---------------------------------------------------------------------------
__global__ void __launch_bounds__(256) attn_vk_kernel() {
    const int g = blockIdx.x, b = blockIdx.y, z = blockIdx.z;
    const int tid = threadIdx.x, lane = tid & 31, wrp = tid >> 5;
    const bf16* mg = g_multi + ((size_t)b * 288 + g * 24) * NPIX;

    float acc[9][8];
    #pragma unroll
    for (int d = 0; d < 9; d++)
        #pragma unroll
        for (int e = 0; e < 8; e++) acc[d][e] = 0.f;

    const int n = z * 1024 + tid * 4;
    float kx[8][4];
    #pragma unroll
    for (int e = 0; e < 8; e++) {
        uint2 kp = *reinterpret_cast<const uint2*>(mg + (8 + e) * NPIX + n);
        const __nv_bfloat162* h = reinterpret_cast<const __nv_bfloat162*>(&kp);
        kx[e][0] = fmaxf(__bfloat162float(h[0].x), 0.f);
        kx[e][1] = fmaxf(__bfloat162float(h[0].y), 0.f);
        kx[e][2] = fmaxf(__bfloat162float(h[1].x), 0.f);
        kx[e][3] = fmaxf(__bfloat162float(h[1].y), 0.f);
    }
    #pragma unroll
    for (int d = 0; d < 8; d++) {
        uint2 vp = *reinterpret_cast<const uint2*>(mg + (16 + d) * NPIX + n);
        const __nv_bfloat162* h = reinterpret_cast<const __nv_bfloat162*>(&vp);
        float v0 = __bfloat162float(h[0].x), v1 = __bfloat162float(h[0].y);
        float v2 = __bfloat162float(h[1].x), v3 = __bfloat162float(h[1].y);
        #pragma unroll
        for (int e = 0; e < 8; e++)
            acc[d][e] = fmaf(v3, kx[e][3], fmaf(v2, kx[e][2],
                        fmaf(v1, kx[e][1], fmaf(v0, kx[e][0], acc[d][e]))));
    }
    #pragma unroll
    for (int e = 0; e < 8; e++)
        acc[8][e] += kx[e][0] + kx[e][1] + kx[e][2] + kx[e][3];

    __shared__ float red[8][72];
    #pragma unroll
    for (int d = 0; d < 9; d++)
        #pragma unroll
        for (int e = 0; e < 8; e++) {
            float s = acc[d][e];
            #pragma unroll
            for (int off = 16; off > 0; off >>= 1) s += __shfl_xor_sync(0xffffffffu, s, off);
            if (lane == 0) red[wrp][d * 8 + e] = s;
        }
    __syncthreads();
    if (tid < 72) {
        float s = 0.f;
        #pragma unroll
        for (int w = 0; w < 8; w++) s += red[w][tid];
        g_vkp[(((size_t)b * NG + g) * 4 + z) * 72 + tid] = s;
    }
}

// ---------------------------------------------------------------------------
// K4b: apply, uint2 q loads, 4 px/thread, z of 4 (1536 blocks), token-major out.
// ---------------------------------------------------------------------------
__global__ void __launch_bounds__(256) attn_apply_kernel() {
    const int g = blockIdx.x, b = blockIdx.y, z = blockIdx.z;
    const int tid = threadIdx.x;
    __shared__ float vk[72];
    if (tid < 72) {
        const float* p = g_vkp + ((size_t)b * NG + g) * 4 * 72 + tid;
        vk[tid] = p[0] + p[72] + p[144] + p[216];
    }
    __syncthreads();
    const bf16* mg = g_multi + ((size_t)b * 288 + g * 24) * NPIX;
    bf16* ab = g_att + ((size_t)b * NPIX) * C3 + g * 8;

    int n = z * 1024 + tid * 4;
    float na[4][8];
    #pragma unroll
    for (int px = 0; px < 4; px++)
        #pragma unroll
        for (int d = 0; d < 8; d++) na[px][d] = 0.f;
    float dd[4] = {1e-15f, 1e-15f, 1e-15f, 1e-15f};
    #pragma unroll
    for (int e = 0; e < 8; e++) {
        uint2 qp = *reinterpret_cast<const uint2*>(mg + e * NPIX + n);
        const __nv_bfloat162* h = reinterpret_cast<const __nv_bfloat162*>(&qp);
        float q[4];
        q[0] = fmaxf(__bfloat162float(h[0].x), 0.f);
        q[1] = fmaxf(__bfloat162float(h[0].y), 0.f);
        q[2] = fmaxf(__bfloat162float(h[1].x), 0.f);
        q[3] = fmaxf(__bfloat162float(h[1].y), 0.f);
        #pragma unroll
        for (int px = 0; px < 4; px++) {
            #pragma unroll
            for (int d = 0; d < 8; d++)
                na[px][d] = fmaf(vk[d * 8 + e], q[px], na[px][d]);
            dd[px] = fmaf(vk[64 + e], q[px], dd[px]);
        }
    }
    #pragma unroll
    for (int px = 0; px < 4; px++) {
        float inv = 1.f / dd[px];
        __nv_bfloat162 p0 = __floats2bfloat162_rn(na[px][0] * inv, na[px][1] * inv);
        __nv_bfloat162 p1 = __floats2bfloat162_rn(na[px][2] * inv, na[px][3] * inv);
        __nv_bfloat162 p2 = __floats2bfloat162_rn(na[px][4] * inv, na[px][5] * inv);
        __nv_bfloat162 p3 = __floats2bfloat162_rn(na[px][6] * inv, na[px][7] * inv);
        uint4 u = make_uint4(*reinterpret_cast<uint32_t*>(&p0), *reinterpret_cast<uint32_t*>(&p1),
                             *reinterpret_cast<uint32_t*>(&p2), *reinterpret_cast<uint32_t*>(&p3));
        *reinterpret_cast<uint4*>(ab + (size_t)(n + px) * C3) = u;
    }
}

// ---------------------------------------------------------------------------
// K5: proj GEMM (M=131072, N=960, K=96) + BN + residual + split.
// Round-12 structure (acc dies before xv is born) + streaming cache hints.
// ---------------------------------------------------------------------------
__global__ void __launch_bounds__(256) proj_gemm_kernel(
    const float* __restrict__ bn_g, const float* __restrict__ bn_b,
    const float* __restrict__ bn_m, const float* __restrict__ bn_v,
    const float* __restrict__ x1, const float* __restrict__ x2, const float* __restrict__ x3,
    float* __restrict__ out) {
    __shared__ union {
        struct { bf16 A[128][104]; bf16 W[96][104]; } s;  // 46592 B
        bf16 C[128][104];
    } sm;
    __shared__ float scv[96], shv[96];
    const int tid  = threadIdx.x;
    const int warp = tid >> 5, lane = tid & 31;
    const int warpM = warp & 3, warpN = warp >> 2;
    const int g = lane >> 2, tg = lane & 3;
    const int o0 = blockIdx.x * 96;
    const int token0 = blockIdx.y * 128;
    const int bb = token0 >> 12;
    const int n0 = token0 & (NPIX - 1);

    if (tid < 96) {
        int o = o0 + tid;
        float sc = bn_g[o] * rsqrtf(bn_v[o] + 1e-5f);
        scv[tid] = sc;
        shv[tid] = bn_b[o] - bn_m[o] * sc;
    }
    for (int idx = tid; idx < 96 * 12; idx += 256) {
        int o = idx / 12, kq = idx % 12;
        uint4 w = *reinterpret_cast<const uint4*>(g_wproj + (size_t)(o0 + o) * 96 + kq * 8);
        *reinterpret_cast<uint4*>(&sm.s.W[o][kq * 8]) = w;
    }
    const bf16* attb = g_att + ((size_t)bb * NPIX + n0) * C3;
    #pragma unroll
    for (int l = 0; l < 6; l++) {
        int idx = tid + l * 256;
        int row = idx / 12, q = idx % 12;
        uint4 v = *reinterpret_cast<const uint4*>(attb + (size_t)row * C3 + q * 8);
        *reinterpret_cast<uint4*>(&sm.s.A[row][q * 8]) = v;
    }
    __syncthreads();

    float acc[2][6][4];
    #pragma unroll
    for (int mr = 0; mr < 2; mr++)
        #pragma unroll
        for (int nb = 0; nb < 6; nb++)
            #pragma unroll
            for (int q = 0; q < 4; q++) acc[mr][nb][q] = 0.f;

    #pragma unroll
    for (int ks = 0; ks < 96; ks += 16) {
        uint32_t afr[2][4], bfr[6][2];
        #pragma unroll
        for (int mr = 0; mr < 2; mr++) {
            int r0 = warpM * 32 + mr * 16;
            afr[mr][0] = *reinterpret_cast<const uint32_t*>(&sm.s.A[r0 + g    ][ks + tg * 2    ]);
            afr[mr][1] = *reinterpret_cast<const uint32_t*>(&sm.s.A[r0 + g + 8][ks + tg * 2    ]);
            afr[mr][2] = *reinterpret_cast<const uint32_t*>(&sm.s.A[r0 + g    ][ks + tg * 2 + 8]);
            afr[mr][3] = *reinterpret_cast<const uint32_t*>(&sm.s.A[r0 + g + 8][ks + tg * 2 + 8]);
        }
        #pragma unroll
        for (int nb = 0; nb < 6; nb++) {
            int o = warpN * 48 + nb * 8 + g;
            bfr[nb][0] = *reinterpret_cast<const uint32_t*>(&sm.s.W[o][ks + tg * 2    ]);
            bfr[nb][1] = *reinterpret_cast<const uint32_t*>(&sm.s.W[o][ks + tg * 2 + 8]);
        }
        #pragma unroll
        for (int mr = 0; mr < 2; mr++)
            #pragma unroll
            for (int nb = 0; nb < 6; nb++)
                mma_bf16(acc[mr][nb], afr[mr], bfr[nb]);
    }
    __syncthreads();
    #pragma unroll
    for (int mr = 0; mr < 2; mr++)
        #pragma unroll
        for (int nb = 0; nb < 6; nb++) {
            int oo = warpN * 48 + nb * 8 + tg * 2;
            int t0 = warpM * 32 + mr * 16 + g;
            __nv_bfloat162 p0 = __floats2bfloat162_rn(acc[mr][nb][0], acc[mr][nb][1]);
            __nv_bfloat162 p1 = __floats2bfloat162_rn(acc[mr][nb][2], acc[mr][nb][3]);
            *reinterpret_cast<uint32_t*>(&sm.C[t0    ][oo]) = *reinterpret_cast<uint32_t*>(&p0);
            *reinterpret_cast<uint32_t*>(&sm.C[t0 + 8][oo]) = *reinterpret_cast<uint32_t*>(&p1);
        }
    __syncthreads();
    // Batched streaming residual loads (__ldcs), then compute + streaming stores.
    float4 xv[12];
    size_t oaddr[12];
    #pragma unroll
    for (int i = 0; i < 12; i++) {
        int idx = tid + i * 256;
        int tl = idx / 24, qo = idx % 24;
        int o_g = o0 + qo * 4;
        int token = token0 + tl;
        const float* xr; size_t obase; int Csz, cl;
        if (o_g < 192)      { xr = x1; obase = 0;                  Csz = 192; cl = o_g; }
        else if (o_g < 448) { xr = x2; obase = (size_t)NTOK * 192; Csz = 256; cl = o_g - 192; }
        else                { xr = x3; obase = (size_t)NTOK * 448; Csz = 512; cl = o_g - 448; }
        size_t base = (size_t)token * Csz + cl;
        xv[i] = __ldcs(reinterpret_cast<const float4*>(xr + base));
        oaddr[i] = obase + base;
    }
    #pragma unroll
    for (int i = 0; i < 12; i++) {
        int idx = tid + i * 256;
        int tl = idx / 24, qo = idx % 24;
        uint2 cu = *reinterpret_cast<const uint2*>(&sm.C[tl][qo * 4]);
        const bf16* ch4 = reinterpret_cast<const bf16*>(&cu);
        int ol = qo * 4;
        float4 ov;
        ov.x = scv[ol    ] * __bfloat162float(ch4[0]) + shv[ol    ] + xv[i].x;
        ov.y = scv[ol + 1] * __bfloat162float(ch4[1]) + shv[ol + 1] + xv[i].y;
        ov.z = scv[ol + 2] * __bfloat162float(ch4[2]) + shv[ol + 2] + xv[i].z;
        ov.w = scv[ol + 3] * __bfloat162float(ch4[3]) + shv[ol + 3] + xv[i].w;
        __stcs(reinterpret_cast<float4*>(out + oaddr[i]), ov);
    }
}

// ---------------------------------------------------------------------------
// Launch
// ---------------------------------------------------------------------------
extern "C" void kernel_launch(void* const* d_in, const int* in_sizes, int n_in,
                              void* d_out, int out_size) {
    (void)out_size;
    const float *x1 = 0, *x2 = 0, *x3 = 0;
    const float *g1 = 0, *b1 = 0, *g2 = 0, *b2 = 0, *g3 = 0, *b3 = 0;
    const float *qkv_w = 0, *dw3 = 0, *pw3 = 0, *dw5 = 0, *pw5 = 0, *proj_w = 0;
    const float *bn_g = 0, *bn_b = 0, *bn_m = 0, *bn_v = 0;
    int c192 = 0, c256 = 0, c512 = 0, cW = 0, c768 = 0, c960 = 0;
    for (int i = 0; i < n_in; i++) {
        const float* p = (const float*)d_in[i];
        switch (in_sizes[i]) {
            case 25165824: x1 = p; break;
            case 33554432: x2 = p; break;
            case 67108864: x3 = p; break;
            case 192: (c192++ ? b1 : g1) = p; break;
            case 256: (c256++ ? b2 : g2) = p; break;
            case 512: (c512++ ? b3 : g3) = p; break;
            case 92160: (cW++ ? proj_w : qkv_w) = p; break;
            case 864:  dw3 = p; break;
            case 2400: dw5 = p; break;
            case 768: (c768++ ? pw5 : pw3) = p; break;
            case 960: {
                if      (c960 == 0) bn_g = p;
                else if (c960 == 1) bn_b = p;
                else if (c960 == 2) bn_m = p;
                else                bn_v = p;
                c960++;
            } break;
            default: break;
        }
    }
    float* out = (float*)d_out;

    norm_kernel<<<NTOK / 8, 256>>>(x1, x2, x3, g1, b1, g2, b2, g3, b3, qkv_w, proj_w);
    qkv_gemm_kernel<<<NTOK / 128, 256>>>();
    dwpw_merged_kernel<<<dim3(4, NG, NB), 256>>>(dw3, pw3, dw5, pw5);
    attn_vk_kernel<<<dim3(NG, NB, 4), 256>>>();
    attn_apply_kernel<<<dim3(NG, NB, 4), 256>>>();
    proj_gemm_kernel<<<dim3(10, NTOK / 128), 256>>>(bn_g, bn_b, bn_m, bn_v,
                                                    x1, x2, x3, out);
}

// round 16
// speedup vs baseline: 1.0423x; 1.0423x over previous
#include <cuda_runtime.h>
#include <cuda_bf16.h>
#include <cstdint>
#include <cstddef>

// ---------------------------------------------------------------------------
#define NB    32
#define NPIX  4096
#define NTOK  (NB*NPIX)   // 131072
#define CIN   960
#define C3    96
#define NG    12
#define HW    64

typedef __nv_bfloat16 bf16;

// ---------------------------------------------------------------------------
// Scratch (device globals)
// ---------------------------------------------------------------------------
__device__ bf16  g_xn   [(size_t)NTOK * CIN];          // LN'd x, [token][960] bf16 (251 MB)
__device__ bf16  g_multi[(size_t)NB * 288 * NPIX];     // [b][ch][n] bf16 (75 MB)
__device__ bf16  g_att  [(size_t)NB * NPIX * C3];      // [b][n][ch] bf16 (25 MB) token-major
__device__ bf16  g_wqkv [C3 * CIN];
__device__ bf16  g_wproj[CIN * C3];
__device__ float g_vkp  [NB * NG * 4 * 72];            // vk partials (4 pixel chunks)

// ---------------------------------------------------------------------------
// K1: LayerNorm, warp-per-token, register-resident (R14 config: no cache hints
// on the g_xn stores — qkv reads them immediately, keep them in L2).
// Also performs weight fp32->bf16 conversion.
// ---------------------------------------------------------------------------
template<int CSZ>
__device__ __forceinline__ void norm_seg(const float* __restrict__ p,
                                         const float* __restrict__ gw,
                                         const float* __restrict__ bw,
                                         bf16* __restrict__ dst, int lane) {
    constexpr int NQ = CSZ / 4;
    constexpr int NI = (NQ + 31) / 32;
    float4 v[NI];
    float sum = 0.f, sq = 0.f;
    #pragma unroll
    for (int i = 0; i < NI; i++) {
        int q = lane + i * 32;
        if ((NQ % 32 == 0) || q < NQ) {
            v[i] = *reinterpret_cast<const float4*>(p + q * 4);
            sum += v[i].x + v[i].y + v[i].z + v[i].w;
            sq  += v[i].x * v[i].x + v[i].y * v[i].y + v[i].z * v[i].z + v[i].w * v[i].w;
        }
    }
    #pragma unroll
    for (int off = 16; off > 0; off >>= 1) {
        sum += __shfl_xor_sync(0xffffffffu, sum, off);
        sq  += __shfl_xor_sync(0xffffffffu, sq,  off);
    }
    float m = sum / (float)CSZ;
    float r = rsqrtf(sq / (float)CSZ - m * m + 1e-6f);
    #pragma unroll
    for (int i = 0; i < NI; i++) {
        int q = lane + i * 32;
        if ((NQ % 32 == 0) || q < NQ) {
            float4 gv = *reinterpret_cast<const float4*>(gw + q * 4);
            float4 bv = *reinterpret_cast<const float4*>(bw + q * 4);
            float f0 = (v[i].x - m) * (r * gv.x) + bv.x;
            float f1 = (v[i].y - m) * (r * gv.y) + bv.y;
            float f2 = (v[i].z - m) * (r * gv.z) + bv.z;
            float f3 = (v[i].w - m) * (r * gv.w) + bv.w;
            __nv_bfloat162 p0 = __floats2bfloat162_rn(f0, f1);
            __nv_bfloat162 p1 = __floats2bfloat162_rn(f2, f3);
            uint2 u = make_uint2(*reinterpret_cast<uint32_t*>(&p0),
                                 *reinterpret_cast<uint32_t*>(&p1));
            *reinterpret_cast<uint2*>(dst + q * 4) = u;
        }
    }
}

__global__ void __launch_bounds__(256) norm_kernel(
    const float* __restrict__ x1, const float* __restrict__ x2, const float* __restrict__ x3,
    const float* __restrict__ g1, const float* __restrict__ b1,
    const float* __restrict__ g2, const float* __restrict__ b2,
    const float* __restrict__ g3, const float* __restrict__ b3,
    const float* __restrict__ qkv_w, const float* __restrict__ proj_w) {
    int gtid = blockIdx.x * 256 + threadIdx.x;
    if (gtid < C3 * CIN) {
        g_wqkv[gtid]  = __float2bfloat16(qkv_w[gtid]);
        g_wproj[gtid] = __float2bfloat16(proj_w[gtid]);
    }
    int t = gtid >> 5;
    int lane = threadIdx.x & 31;
    bf16* dst = g_xn + (size_t)t * CIN;
    norm_seg<192>(x1 + (size_t)t * 192, g1, b1, dst,       lane);
    norm_seg<256>(x2 + (size_t)t * 256, g2, b2, dst + 192, lane);
    norm_seg<512>(x3 + (size_t)t * 512, g3, b3, dst + 448, lane);
}

// ---------------------------------------------------------------------------
// mma.sync m16n8k16 bf16 helper
// ---------------------------------------------------------------------------
__device__ __forceinline__ void mma_bf16(float* c, const uint32_t* a, const uint32_t* b) {
    asm volatile(
        "mma.sync.aligned.m16n8k16.row.col.f32.bf16.bf16.f32 "
        "{%0,%1,%2,%3}, {%4,%5,%6,%7}, {%8,%9}, {%0,%1,%2,%3};\n"
        : "+f"(c[0]), "+f"(c[1]), "+f"(c[2]), "+f"(c[3])
        : "r"(a[0]), "r"(a[1]), "r"(a[2]), "r"(a[3]), "r"(b[0]), "r"(b[1]));
}

__device__ __forceinline__ void cp16(uint32_t smem_addr, const void* gptr) {
    asm volatile("cp.async.cg.shared.global [%0], [%1], 16;\n"
                 :: "r"(smem_addr), "l"(gptr));
}

// ---------------------------------------------------------------------------
// K2: qkv GEMM (M=131072, N=96, K=960), bf16 A from g_xn, ldmatrix fragments,
// 2-stage cp.async double-buffer with K-tile 64 (15 iterations, half the
// barrier/wait overhead of the 32-wide version). Dynamic smem (63 KB).
// Stride 72 bf16 per row: cp.async 16B-aligned, ldmatrix conflict-free.
// ---------------------------------------------------------------------------
#define QKV_SMEM (2*128*72*2 + 2*96*72*2)   // 64512 B

__global__ void __launch_bounds__(256) qkv_gemm_kernel() {
    extern __shared__ char dyn[];
    bf16* As = reinterpret_cast<bf16*>(dyn);                 // [2][128][72]
    bf16* Ws = As + 2 * 128 * 72;                            // [2][96][72]
    bf16* Cs = reinterpret_cast<bf16*>(dyn);                 // [96][136] (reuse)
    const int tid  = threadIdx.x;
    const int warp = tid >> 5, lane = tid & 31;
    const int warpM = warp & 3, warpN = warp >> 2;
    const int g = lane >> 2, tg = lane & 3;
    const int token0 = blockIdx.x * 128;
    const bf16* An = g_xn + (size_t)token0 * CIN;

    const int lr = lane & 7;
    const int lg = lane >> 3;
    const int a_row = warpM * 32 + lr + ((lane >> 3) & 1) * 8;
    const int a_col = (lane >> 4) * 8;
    const int b_blk = (lg >> 1);
    const int b_col = (lg & 1) * 8;

    uint32_t Abase, Wbase;
    {
        uint64_t a64 = __cvta_generic_to_shared(As);
        uint64_t w64 = __cvta_generic_to_shared(Ws);
        Abase = (uint32_t)a64;
        Wbase = (uint32_t)w64;
    }

    float acc[2][6][4];
    #pragma unroll
    for (int mr = 0; mr < 2; mr++)
        #pragma unroll
        for (int nb = 0; nb < 6; nb++)
            #pragma unroll
            for (int q = 0; q < 4; q++) acc[mr][nb][q] = 0.f;

    auto load_tile = [&](int kt, int sb) {
        const int k0 = kt * 64;
        const uint32_t Aoff = Abase + (uint32_t)(sb * 128 * 72 * 2);
        const uint32_t Woff = Wbase + (uint32_t)(sb * 96 * 72 * 2);
        #pragma unroll
        for (int l = 0; l < 4; l++) {            // A: 1024 x 16B chunks
            int c = tid + l * 256;
            int row = c >> 3, q = c & 7;
            cp16(Aoff + (uint32_t)((row * 72 + q * 8) * 2),
                 An + (size_t)row * CIN + k0 + q * 8);
        }
        #pragma unroll
        for (int l = 0; l < 3; l++) {            // W: 768 x 16B chunks
            int c = tid + l * 256;
            int o = c >> 3, q = c & 7;
            cp16(Woff + (uint32_t)((o * 72 + q * 8) * 2),
                 g_wqkv + (size_t)o * CIN + k0 + q * 8);
        }
    };

    load_tile(0, 0);
    asm volatile("cp.async.commit_group;\n" ::: "memory");

    for (int kt = 0; kt < 15; kt++) {
        const int sb = kt & 1;
        if (kt < 14) {
            load_tile(kt + 1, sb ^ 1);
            asm volatile("cp.async.commit_group;\n" ::: "memory");
            asm volatile("cp.async.wait_group 1;\n" ::: "memory");
        } else {
            asm volatile("cp.async.wait_group 0;\n" ::: "memory");
        }
        __syncthreads();
        const uint32_t Aoff = Abase + (uint32_t)(sb * 128 * 72 * 2);
        const uint32_t Woff = Wbase + (uint32_t)(sb * 96 * 72 * 2);
        #pragma unroll
        for (int ks = 0; ks < 64; ks += 16) {
            uint32_t afr[2][4], bfr[6][2];
            #pragma unroll
            for (int mr = 0; mr < 2; mr++) {
                uint32_t addr = Aoff + (uint32_t)(((a_row + mr * 16) * 72 + ks + a_col) * 2);
                asm volatile(
                    "ldmatrix.sync.aligned.m8n8.x4.shared.b16 {%0,%1,%2,%3}, [%4];"
                    : "=r"(afr[mr][0]), "=r"(afr[mr][1]), "=r"(afr[mr][2]), "=r"(afr[mr][3])
                    : "r"(addr));
            }
            #pragma unroll
            for (int nb2 = 0; nb2 < 3; nb2++) {
                uint32_t addr = Woff + (uint32_t)((((warpN * 48 + (nb2 * 2 + b_blk) * 8 + lr) * 72)
                                                    + ks + b_col) * 2);
                asm volatile(
                    "ldmatrix.sync.aligned.m8n8.x4.shared.b16 {%0,%1,%2,%3}, [%4];"
                    : "=r"(bfr[nb2 * 2][0]), "=r"(bfr[nb2 * 2][1]),
                      "=r"(bfr[nb2 * 2 + 1][0]), "=r"(bfr[nb2 * 2 + 1][1])
                    : "r"(addr));
            }
            #pragma unroll
            for (int mr = 0; mr < 2; mr++)
                #pragma unroll
                for (int nb = 0; nb < 6; nb++)
                    mma_bf16(acc[mr][nb], afr[mr], bfr[nb]);
        }
        __syncthreads();
    }
    // Stage C to smem [o][tok] (stride 136) then coalesced uint4 stores
    #pragma unroll
    for (int mr = 0; mr < 2; mr++)
        #pragma unroll
        for (int nb = 0; nb < 6; nb++) {
            int oo = warpN * 48 + nb * 8 + tg * 2;
            int t0 = warpM * 32 + mr * 16 + g;
            Cs[(oo    ) * 136 + t0    ] = __float2bfloat16(acc[mr][nb][0]);
            Cs[(oo + 1) * 136 + t0    ] = __float2bfloat16(acc[mr][nb][1]);
            Cs[(oo    ) * 136 + t0 + 8] = __float2bfloat16(acc[mr][nb][2]);
            Cs[(oo + 1) * 136 + t0 + 8] = __float2bfloat16(acc[mr][nb][3]);
        }
    __syncthreads();
    const int bb = token0 >> 12;
    const int n0 = token0 & (NPIX - 1);
    #pragma unroll
    for (int i = 0; i < 6; i++) {
        int idx = tid + i * 256;
        int o = idx >> 4, q = idx & 15;
        uint4 v = *reinterpret_cast<const uint4*>(&Cs[o * 136 + q * 8]);
        *reinterpret_cast<uint4*>(g_multi + ((size_t)bb * 288 + o) * NPIX + n0 + q * 8) = v;
    }
}

// ---------------------------------------------------------------------------
// K3: MERGED dw3+pw3 and dw5+pw5 (measured 55us; unchanged).
// ---------------------------------------------------------------------------
__global__ void __launch_bounds__(256, 4) dwpw_merged_kernel(
        const float* __restrict__ dw3_w, const float* __restrict__ pw3_w,
        const float* __restrict__ dw5_w, const float* __restrict__ pw5_w) {
    constexpr int T = 36;
    __shared__ float sin_[8][T][T];
    __shared__ float wd3[8][9], wd5[8][25];
    __shared__ __nv_bfloat162 wp3p[8][8], wp5p[8][8];
    const int b = blockIdx.z, g = blockIdx.y, tile = blockIdx.x;
    const int ty0 = (tile >> 1) * 32, tx0 = (tile & 1) * 32;
    const int tid = threadIdx.x;
    const bf16* src = g_multi + ((size_t)b * 288 + g * 8) * NPIX;

    for (int idx = tid; idx < 8 * T * T; idx += 256) {
        int ch = idx / (T * T); int rem = idx - ch * T * T;
        int yy = rem / T, xx = rem - yy * T;
        int gy = ty0 + yy - 2, gx = tx0 + xx - 2;
        float v = 0.f;
        if (gy >= 0 && gy < HW && gx >= 0 && gx < HW)
            v = __bfloat162float(src[ch * NPIX + gy * HW + gx]);
        sin_[ch][yy][xx] = v;
    }
    if (tid < 72) { int ch = tid / 9, kk = tid % 9; wd3[ch][kk] = dw3_w[(g * 8 + ch) * 9 + kk]; }
    else if (tid < 136) {
        int t = tid - 72;
        wp3p[t & 7][t >> 3] = __float2bfloat162_rn(pw3_w[(g * 8 + (t >> 3)) * 8 + (t & 7)]);
    } else if (tid < 200) {
        int t = tid - 136;
        wp5p[t & 7][t >> 3] = __float2bfloat162_rn(pw5_w[(g * 8 + (t >> 3)) * 8 + (t & 7)]);
    }
    for (int t = tid; t < 200; t += 256) {
        int ch = t / 25, kk = t % 25;
        wd5[ch][kk] = dw5_w[(g * 8 + ch) * 25 + kk];
    }
    __syncthreads();

    const int py  = tid >> 3;
    const int px0 = (tid & 7) * 4;
    __nv_bfloat162 o3p[2][8], o5p[2][8];
    const __nv_bfloat162 z2 = __float2bfloat162_rn(0.f);
    #pragma unroll
    for (int j = 0; j < 2; j++)
        #pragma unroll
        for (int o = 0; o < 8; o++) { o3p[j][o] = z2; o5p[j][o] = z2; }

    #pragma unroll 1
    for (int ch = 0; ch < 8; ch++) {
        float s5[4] = {0.f, 0.f, 0.f, 0.f};
        float s3[4] = {0.f, 0.f, 0.f, 0.f};
        #pragma unroll
        for (int r = 0; r < 5; r++) {
            float4 a = *reinterpret_cast<const float4*>(&sin_[ch][py + r][px0]);
            float4 c4 = *reinterpret_cast<const float4*>(&sin_[ch][py + r][px0 + 4]);
            float w[8] = {a.x, a.y, a.z, a.w, c4.x, c4.y, c4.z, c4.w};
            #pragma unroll
            for (int j = 0; j < 4; j++) {
                float t = 0.f;
                #pragma unroll
                for (int c = 0; c < 5; c++) t = fmaf(w[c + j], wd5[ch][r * 5 + c], t);
                s5[j] += t;
            }
            if (r >= 1 && r <= 3) {
                #pragma unroll
                for (int j = 0; j < 4; j++) {
                    float t = 0.f;
                    #pragma unroll
                    for (int c = 0; c < 3; c++) t = fmaf(w[c + j + 1], wd3[ch][(r - 1) * 3 + c], t);
                    s3[j] += t;
                }
            }
        }
        __nv_bfloat162 s3a = __floats2bfloat162_rn(s3[0], s3[1]);
        __nv_bfloat162 s3b = __floats2bfloat162_rn(s3[2], s3[3]);
        __nv_bfloat162 s5a = __floats2bfloat162_rn(s5[0], s5[1]);
        __nv_bfloat162 s5b = __floats2bfloat162_rn(s5[2], s5[3]);
        #pragma unroll
        for (int o = 0; o < 8; o++) {
            o3p[0][o] = __hfma2(wp3p[ch][o], s3a, o3p[0][o]);
            o3p[1][o] = __hfma2(wp3p[ch][o], s3b, o3p[1][o]);
            o5p[0][o] = __hfma2(wp5p[ch][o], s5a, o5p[0][o]);
            o5p[1][o] = __hfma2(wp5p[ch][o], s5b, o5p[1][o]);
        }
    }
    bf16* dst3 = g_multi + ((size_t)b * 288 +  96 + g * 8) * NPIX;
    bf16* dst5 = g_multi + ((size_t)b * 288 + 192 + g * 8) * NPIX;
    int n = (ty0 + py) * HW + (tx0 + px0);
    #pragma unroll
    for (int o = 0; o < 8; o++) {
        uint2 u3 = make_uint2(*reinterpret_cast<uint32_t*>(&o3p[0][o]),
                              *reinterpret_cast<uint32_t*>(&o3p[1][o]));
        *reinterpret_cast<uint2*>(dst3 + o * NPIX + n) = u3;
        uint2 u5 = make_uint2(*reinterpret_cast<uint32_t*>(&o5p[0][o]),
                              *reinterpret_cast<uint32_t*>(&o5p[1][o]));
        *reinterpret_cast<uint2*>(dst5 + o * NPIX + n) = u5;
    }
}

// ---------------------------------------------------------------------------
// K4a: vk partials per (b, g, z of 4). uint2 loads, 4 px/thread, single pass.
// ---------------------------------------------------------------------------
__global__ void __launch_bounds__(256) attn_vk_kernel() {
    const int g = blockIdx.x, b = blockIdx.y, z = blockIdx.z;
    const int tid = threadIdx.x, lane = tid & 31, wrp = tid >> 5;
    const bf16* mg = g_multi + ((size_t)b * 288 + g * 24) * NPIX;

    float acc[9][8];
    #pragma unroll
    for (int d = 0; d < 9; d++)
        #pragma unroll
        for (int e = 0; e < 8; e++) acc[d][e] = 0.f;

    const int n = z * 1024 + tid * 4;
    float kx[8][4];
    #pragma unroll
    for (int e = 0; e < 8; e++) {
        uint2 kp = *reinterpret_cast<const uint2*>(mg + (8 + e) * NPIX + n);
        const __nv_bfloat162* h = reinterpret_cast<const __nv_bfloat162*>(&kp);
        kx[e][0] = fmaxf(__bfloat162float(h[0].x), 0.f);
        kx[e][1] = fmaxf(__bfloat162float(h[0].y), 0.f);
        kx[e][2] = fmaxf(__bfloat162float(h[1].x), 0.f);
        kx[e][3] = fmaxf(__bfloat162float(h[1].y), 0.f);
    }
    #pragma unroll
    for (int d = 0; d < 8; d++) {
        uint2 vp = *reinterpret_cast<const uint2*>(mg + (16 + d) * NPIX + n);
        const __nv_bfloat162* h = reinterpret_cast<const __nv_bfloat162*>(&vp);
        float v0 = __bfloat162float(h[0].x), v1 = __bfloat162float(h[0].y);
        float v2 = __bfloat162float(h[1].x), v3 = __bfloat162float(h[1].y);
        #pragma unroll
        for (int e = 0; e < 8; e++)
            acc[d][e] = fmaf(v3, kx[e][3], fmaf(v2, kx[e][2],
                        fmaf(v1, kx[e][1], fmaf(v0, kx[e][0], acc[d][e]))));
    }
    #pragma unroll
    for (int e = 0; e < 8; e++)
        acc[8][e] += kx[e][0] + kx[e][1] + kx[e][2] + kx[e][3];

    __shared__ float red[8][72];
    #pragma unroll
    for (int d = 0; d < 9; d++)
        #pragma unroll
        for (int e = 0; e < 8; e++) {
            float s = acc[d][e];
            #pragma unroll
            for (int off = 16; off > 0; off >>= 1) s += __shfl_xor_sync(0xffffffffu, s, off);
            if (lane == 0) red[wrp][d * 8 + e] = s;
        }
    __syncthreads();
    if (tid < 72) {
        float s = 0.f;
        #pragma unroll
        for (int w = 0; w < 8; w++) s += red[w][tid];
        g_vkp[(((size_t)b * NG + g) * 4 + z) * 72 + tid] = s;
    }
}

// ---------------------------------------------------------------------------
// K4b: apply (R14 config: z of 2, it loop of 2), token-major g_att out.
// ---------------------------------------------------------------------------
__global__ void __launch_bounds__(256) attn_apply_kernel() {
    const int g = blockIdx.x, b = blockIdx.y, z = blockIdx.z;
    const int tid = threadIdx.x;
    __shared__ float vk[72];
    if (tid < 72) {
        const float* p = g_vkp + ((size_t)b * NG + g) * 4 * 72 + tid;
        vk[tid] = p[0] + p[72] + p[144] + p[216];
    }
    __syncthreads();
    const bf16* mg = g_multi + ((size_t)b * 288 + g * 24) * NPIX;
    bf16* ab = g_att + ((size_t)b * NPIX) * C3 + g * 8;

    #pragma unroll
    for (int it = 0; it < 2; it++) {
        int n = z * 2048 + it * 1024 + tid * 4;
        float na[4][8];
        #pragma unroll
        for (int px = 0; px < 4; px++)
            #pragma unroll
            for (int d = 0; d < 8; d++) na[px][d] = 0.f;
        float dd[4] = {1e-15f, 1e-15f, 1e-15f, 1e-15f};
        #pragma unroll
        for (int e = 0; e < 8; e++) {
            uint2 qp = *reinterpret_cast<const uint2*>(mg + e * NPIX + n);
            const __nv_bfloat162* h = reinterpret_cast<const __nv_bfloat162*>(&qp);
            float q[4];
            q[0] = fmaxf(__bfloat162float(h[0].x), 0.f);
            q[1] = fmaxf(__bfloat162float(h[0].y), 0.f);
            q[2] = fmaxf(__bfloat162float(h[1].x), 0.f);
            q[3] = fmaxf(__bfloat162float(h[1].y), 0.f);
            #pragma unroll
            for (int px = 0; px < 4; px++) {
                #pragma unroll
                for (int d = 0; d < 8; d++)
                    na[px][d] = fmaf(vk[d * 8 + e], q[px], na[px][d]);
                dd[px] = fmaf(vk[64 + e], q[px], dd[px]);
            }
        }
        #pragma unroll
        for (int px = 0; px < 4; px++) {
            float inv = 1.f / dd[px];
            __nv_bfloat162 p0 = __floats2bfloat162_rn(na[px][0] * inv, na[px][1] * inv);
            __nv_bfloat162 p1 = __floats2bfloat162_rn(na[px][2] * inv, na[px][3] * inv);
            __nv_bfloat162 p2 = __floats2bfloat162_rn(na[px][4] * inv, na[px][5] * inv);
            __nv_bfloat162 p3 = __floats2bfloat162_rn(na[px][6] * inv, na[px][7] * inv);
            uint4 u = make_uint4(*reinterpret_cast<uint32_t*>(&p0), *reinterpret_cast<uint32_t*>(&p1),
                                 *reinterpret_cast<uint32_t*>(&p2), *reinterpret_cast<uint32_t*>(&p3));
            *reinterpret_cast<uint4*>(ab + (size_t)(n + px) * C3) = u;
        }
    }
}

// ---------------------------------------------------------------------------
// K5: proj GEMM (M=131072, N=960, K=96) + BN + residual + split.
// R12 structure + streaming cache hints (measured best).
// ---------------------------------------------------------------------------
__global__ void __launch_bounds__(256) proj_gemm_kernel(
    const float* __restrict__ bn_g, const float* __restrict__ bn_b,
    const float* __restrict__ bn_m, const float* __restrict__ bn_v,
    const float* __restrict__ x1, const float* __restrict__ x2, const float* __restrict__ x3,
    float* __restrict__ out) {
    __shared__ union {
        struct { bf16 A[128][104]; bf16 W[96][104]; } s;  // 46592 B
        bf16 C[128][104];
    } sm;
    __shared__ float scv[96], shv[96];
    const int tid  = threadIdx.x;
    const int warp = tid >> 5, lane = tid & 31;
    const int warpM = warp & 3, warpN = warp >> 2;
    const int g = lane >> 2, tg = lane & 3;
    const int o0 = blockIdx.x * 96;
    const int token0 = blockIdx.y * 128;
    const int bb = token0 >> 12;
    const int n0 = token0 & (NPIX - 1);

    if (tid < 96) {
        int o = o0 + tid;
        float sc = bn_g[o] * rsqrtf(bn_v[o] + 1e-5f);
        scv[tid] = sc;
        shv[tid] = bn_b[o] - bn_m[o] * sc;
    }
    for (int idx = tid; idx < 96 * 12; idx += 256) {
        int o = idx / 12, kq = idx % 12;
        uint4 w = *reinterpret_cast<const uint4*>(g_wproj + (size_t)(o0 + o) * 96 + kq * 8);
        *reinterpret_cast<uint4*>(&sm.s.W[o][kq * 8]) = w;
    }
    const bf16* attb = g_att + ((size_t)bb * NPIX + n0) * C3;
    #pragma unroll
    for (int l = 0; l < 6; l++) {
        int idx = tid + l * 256;
        int row = idx / 12, q = idx % 12;
        uint4 v = *reinterpret_cast<const uint4*>(attb + (size_t)row * C3 + q * 8);
        *reinterpret_cast<uint4*>(&sm.s.A[row][q * 8]) = v;
    }
    __syncthreads();

    float acc[2][6][4];
    #pragma unroll
    for (int mr = 0; mr < 2; mr++)
        #pragma unroll
        for (int nb = 0; nb < 6; nb++)
            #pragma unroll
            for (int q = 0; q < 4; q++) acc[mr][nb][q] = 0.f;

    #pragma unroll
    for (int ks = 0; ks < 96; ks += 16) {
        uint32_t afr[2][4], bfr[6][2];
        #pragma unroll
        for (int mr = 0; mr < 2; mr++) {
            int r0 = warpM * 32 + mr * 16;
            afr[mr][0] = *reinterpret_cast<const uint32_t*>(&sm.s.A[r0 + g    ][ks + tg * 2    ]);
            afr[mr][1] = *reinterpret_cast<const uint32_t*>(&sm.s.A[r0 + g + 8][ks + tg * 2    ]);
            afr[mr][2] = *reinterpret_cast<const uint32_t*>(&sm.s.A[r0 + g    ][ks + tg * 2 + 8]);
            afr[mr][3] = *reinterpret_cast<const uint32_t*>(&sm.s.A[r0 + g + 8][ks + tg * 2 + 8]);
        }
        #pragma unroll
        for (int nb = 0; nb < 6; nb++) {
            int o = warpN * 48 + nb * 8 + g;
            bfr[nb][0] = *reinterpret_cast<const uint32_t*>(&sm.s.W[o][ks + tg * 2    ]);
            bfr[nb][1] = *reinterpret_cast<const uint32_t*>(&sm.s.W[o][ks + tg * 2 + 8]);
        }
        #pragma unroll
        for (int mr = 0; mr < 2; mr++)
            #pragma unroll
            for (int nb = 0; nb < 6; nb++)
                mma_bf16(acc[mr][nb], afr[mr], bfr[nb]);
    }
    __syncthreads();
    #pragma unroll
    for (int mr = 0; mr < 2; mr++)
        #pragma unroll
        for (int nb = 0; nb < 6; nb++) {
            int oo = warpN * 48 + nb * 8 + tg * 2;
            int t0 = warpM * 32 + mr * 16 + g;
            __nv_bfloat162 p0 = __floats2bfloat162_rn(acc[mr][nb][0], acc[mr][nb][1]);
            __nv_bfloat162 p1 = __floats2bfloat162_rn(acc[mr][nb][2], acc[mr][nb][3]);
            *reinterpret_cast<uint32_t*>(&sm.C[t0    ][oo]) = *reinterpret_cast<uint32_t*>(&p0);
            *reinterpret_cast<uint32_t*>(&sm.C[t0 + 8][oo]) = *reinterpret_cast<uint32_t*>(&p1);
        }
    __syncthreads();
    float4 xv[12];
    size_t oaddr[12];
    #pragma unroll
    for (int i = 0; i < 12; i++) {
        int idx = tid + i * 256;
        int tl = idx / 24, qo = idx % 24;
        int o_g = o0 + qo * 4;
        int token = token0 + tl;
        const float* xr; size_t obase; int Csz, cl;
        if (o_g < 192)      { xr = x1; obase = 0;                  Csz = 192; cl = o_g; }
        else if (o_g < 448) { xr = x2; obase = (size_t)NTOK * 192; Csz = 256; cl = o_g - 192; }
        else                { xr = x3; obase = (size_t)NTOK * 448; Csz = 512; cl = o_g - 448; }
        size_t base = (size_t)token * Csz + cl;
        xv[i] = __ldcs(reinterpret_cast<const float4*>(xr + base));
        oaddr[i] = obase + base;
    }
    #pragma unroll
    for (int i = 0; i < 12; i++) {
        int idx = tid + i * 256;
        int tl = idx / 24, qo = idx % 24;
        uint2 cu = *reinterpret_cast<const uint2*>(&sm.C[tl][qo * 4]);
        const bf16* ch4 = reinterpret_cast<const bf16*>(&cu);
        int ol = qo * 4;
        float4 ov;
        ov.x = scv[ol    ] * __bfloat162float(ch4[0]) + shv[ol    ] + xv[i].x;
        ov.y = scv[ol + 1] * __bfloat162float(ch4[1]) + shv[ol + 1] + xv[i].y;
        ov.z = scv[ol + 2] * __bfloat162float(ch4[2]) + shv[ol + 2] + xv[i].z;
        ov.w = scv[ol + 3] * __bfloat162float(ch4[3]) + shv[ol + 3] + xv[i].w;
        __stcs(reinterpret_cast<float4*>(out + oaddr[i]), ov);
    }
}

// ---------------------------------------------------------------------------
// Launch
// ---------------------------------------------------------------------------
extern "C" void kernel_launch(void* const* d_in, const int* in_sizes, int n_in,
                              void* d_out, int out_size) {
    (void)out_size;
    const float *x1 = 0, *x2 = 0, *x3 = 0;
    const float *g1 = 0, *b1 = 0, *g2 = 0, *b2 = 0, *g3 = 0, *b3 = 0;
    const float *qkv_w = 0, *dw3 = 0, *pw3 = 0, *dw5 = 0, *pw5 = 0, *proj_w = 0;
    const float *bn_g = 0, *bn_b = 0, *bn_m = 0, *bn_v = 0;
    int c192 = 0, c256 = 0, c512 = 0, cW = 0, c768 = 0, c960 = 0;
    for (int i = 0; i < n_in; i++) {
        const float* p = (const float*)d_in[i];
        switch (in_sizes[i]) {
            case 25165824: x1 = p; break;
            case 33554432: x2 = p; break;
            case 67108864: x3 = p; break;
            case 192: (c192++ ? b1 : g1) = p; break;
            case 256: (c256++ ? b2 : g2) = p; break;
            case 512: (c512++ ? b3 : g3) = p; break;
            case 92160: (cW++ ? proj_w : qkv_w) = p; break;
            case 864:  dw3 = p; break;
            case 2400: dw5 = p; break;
            case 768: (c768++ ? pw5 : pw3) = p; break;
            case 960: {
                if      (c960 == 0) bn_g = p;
                else if (c960 == 1) bn_b = p;
                else if (c960 == 2) bn_m = p;
                else                bn_v = p;
                c960++;
            } break;
            default: break;
        }
    }
    float* out = (float*)d_out;

    // opt-in to >48KB dynamic smem for the qkv GEMM (idempotent, not a stream op)
    cudaFuncSetAttribute(qkv_gemm_kernel,
                         cudaFuncAttributeMaxDynamicSharedMemorySize, QKV_SMEM);

    norm_kernel<<<NTOK / 8, 256>>>(x1, x2, x3, g1, b1, g2, b2, g3, b3, qkv_w, proj_w);
    qkv_gemm_kernel<<<NTOK / 128, 256, QKV_SMEM>>>();
    dwpw_merged_kernel<<<dim3(4, NG, NB), 256>>>(dw3, pw3, dw5, pw5);
    attn_vk_kernel<<<dim3(NG, NB, 4), 256>>>();
    attn_apply_kernel<<<dim3(NG, NB, 2), 256>>>();
    proj_gemm_kernel<<<dim3(10, NTOK / 128), 256>>>(bn_g, bn_b, bn_m, bn_v,
                                                    x1, x2, x3, out);
}